// round 2
// baseline (speedup 1.0000x reference)
#include <cuda_runtime.h>
#include <cuda_bf16.h>
#include <math.h>

// Problem constants
#define T_DIM 1024
#define S_DIM 128
#define H_DIM 512
#define LN_EPS 1e-5f

// Scratch (allocation-free rule: __device__ globals)
__device__ float d_gt[T_DIM * H_DIM];   // text  @ wt^T   (1024 x 512)
__device__ float d_gs[S_DIM * H_DIM];   // struct @ ws^T  (128  x 512)

// ---------------------------------------------------------------------------
// GEMM: C[r,i] = sum_k A[r,k] * gate_w[i*1024 + woff + k]
// A row-major (M x 512). gate_w row-major (512 x 1024), woff selects wt/ws.
// Tiles: 64x64, K-tile 16, 256 threads, each computes 4x4.
// which==0 -> write d_gt, which==1 -> write d_gs
// ---------------------------------------------------------------------------
#define BM 64
#define BN 64
#define BK 16

__global__ __launch_bounds__(256) void gemm_tn_kernel(
    const float* __restrict__ A, const float* __restrict__ W,
    int woff, int which)
{
    __shared__ float As[BM][BK + 1];
    __shared__ float Bs[BN][BK + 1];

    float* __restrict__ C = which ? d_gs : d_gt;

    const int tx = threadIdx.x;          // 0..15 (N dir)
    const int ty = threadIdx.y;          // 0..15 (M dir)
    const int tid = ty * 16 + tx;        // 0..255
    const int brow = blockIdx.y * BM;
    const int bcol = blockIdx.x * BN;

    float acc[4][4];
    #pragma unroll
    for (int i = 0; i < 4; i++)
        #pragma unroll
        for (int j = 0; j < 4; j++) acc[i][j] = 0.f;

    for (int k0 = 0; k0 < H_DIM; k0 += BK) {
        // Load 64x16 A tile and 64x16 B tile (1024 floats each, 4 per thread)
        #pragma unroll
        for (int i = 0; i < 4; i++) {
            int idx = tid + i * 256;
            int r = idx / BK, c = idx % BK;
            As[r][c] = A[(size_t)(brow + r) * H_DIM + k0 + c];
            Bs[r][c] = W[(size_t)(bcol + r) * 1024 + woff + k0 + c];
        }
        __syncthreads();

        #pragma unroll
        for (int k = 0; k < BK; k++) {
            float a[4], b[4];
            #pragma unroll
            for (int i = 0; i < 4; i++) a[i] = As[ty * 4 + i][k];
            #pragma unroll
            for (int j = 0; j < 4; j++) b[j] = Bs[tx * 4 + j][k];
            #pragma unroll
            for (int i = 0; i < 4; i++)
                #pragma unroll
                for (int j = 0; j < 4; j++)
                    acc[i][j] = fmaf(a[i], b[j], acc[i][j]);
        }
        __syncthreads();
    }

    #pragma unroll
    for (int i = 0; i < 4; i++) {
        int r = brow + ty * 4 + i;
        #pragma unroll
        for (int j = 0; j < 4; j++) {
            int c = bcol + tx * 4 + j;
            C[(size_t)r * H_DIM + c] = acc[i][j];
        }
    }
}

// ---------------------------------------------------------------------------
// Fused: gates = relu(gt[t,h] + gs[s,h] + b[h]) * mask[t,s]
//        enrichment[t,h] = sum_s gates[t,s,h] * struct[s,h]
//        enriched = LayerNorm(text + enrichment)
// One block handles TB=4 t-rows; 512 threads = one per h.
// ---------------------------------------------------------------------------
#define TB 4

__global__ __launch_bounds__(512) void fuse_kernel(
    const float* __restrict__ text,
    const float* __restrict__ sstruct,
    const int*   __restrict__ mask,
    const float* __restrict__ gate_b,
    const float* __restrict__ gamma,
    const float* __restrict__ beta,
    float* __restrict__ enriched,   // (T, H)
    float* __restrict__ gates)      // (T, S, H)
{
    const int h  = threadIdx.x;           // 0..511
    const int t0 = blockIdx.x * TB;

    __shared__ float msk[TB][S_DIM];
    __shared__ float red[2][TB][16];

    // Load mask tile (as float 0/1)
    for (int i = h; i < TB * S_DIM; i += H_DIM) {
        int tt = i / S_DIM, s = i % S_DIM;
        msk[tt][s] = (float)mask[(size_t)(t0 + tt) * S_DIM + s];
    }
    __syncthreads();

    const float bh = gate_b[h];
    float gtb[TB], acc[TB];
    #pragma unroll
    for (int tt = 0; tt < TB; tt++) {
        gtb[tt] = d_gt[(size_t)(t0 + tt) * H_DIM + h] + bh;
        acc[tt] = 0.f;
    }

    #pragma unroll 4
    for (int s = 0; s < S_DIM; s++) {
        const float gsv = d_gs[(size_t)s * H_DIM + h];
        const float sv  = sstruct[(size_t)s * H_DIM + h];
        #pragma unroll
        for (int tt = 0; tt < TB; tt++) {
            float g = fmaxf(gtb[tt] + gsv, 0.f) * msk[tt][s];
            gates[((size_t)(t0 + tt) * S_DIM + s) * H_DIM + h] = g;
            acc[tt] = fmaf(g, sv, acc[tt]);
        }
    }

    // LayerNorm over h for each of the TB rows
    const int lane = h & 31, warp = h >> 5;
    float xv[TB];
    #pragma unroll
    for (int tt = 0; tt < TB; tt++) {
        float x = text[(size_t)(t0 + tt) * H_DIM + h] + acc[tt];
        xv[tt] = x;
        float s1 = x, s2 = x * x;
        #pragma unroll
        for (int o = 16; o > 0; o >>= 1) {
            s1 += __shfl_xor_sync(0xFFFFFFFFu, s1, o);
            s2 += __shfl_xor_sync(0xFFFFFFFFu, s2, o);
        }
        if (lane == 0) { red[0][tt][warp] = s1; red[1][tt][warp] = s2; }
    }
    __syncthreads();

    const float gm = gamma[h], bt = beta[h];
    #pragma unroll
    for (int tt = 0; tt < TB; tt++) {
        float s1 = 0.f, s2 = 0.f;
        #pragma unroll
        for (int w = 0; w < 16; w++) { s1 += red[0][tt][w]; s2 += red[1][tt][w]; }
        float mu  = s1 * (1.f / H_DIM);
        float var = s2 * (1.f / H_DIM) - mu * mu;
        float inv = rsqrtf(var + LN_EPS);
        enriched[(size_t)(t0 + tt) * H_DIM + h] = (xv[tt] - mu) * inv * gm + bt;
    }
}

// ---------------------------------------------------------------------------
// Launch
// inputs: 0 text_embeds (T,H) f32 | 1 struct_embeds (S,H) f32 | 2 mask (T,S) i32
//         3 gate_w (H,2H) f32 | 4 gate_b (H) | 5 ln_gamma (H) | 6 ln_beta (H)
// output: enriched (T*H) floats followed by gates (T*S*H) floats
// ---------------------------------------------------------------------------
extern "C" void kernel_launch(void* const* d_in, const int* in_sizes, int n_in,
                              void* d_out, int out_size)
{
    const float* text    = (const float*)d_in[0];
    const float* sstruct = (const float*)d_in[1];
    const int*   mask    = (const int*)  d_in[2];
    const float* gate_w  = (const float*)d_in[3];
    const float* gate_b  = (const float*)d_in[4];
    const float* gamma   = (const float*)d_in[5];
    const float* beta    = (const float*)d_in[6];

    float* enriched = (float*)d_out;
    float* gates    = (float*)d_out + (size_t)T_DIM * H_DIM;

    // gt = text @ wt^T   (woff=0)
    {
        dim3 blk(16, 16);
        dim3 grd(H_DIM / BN, T_DIM / BM);
        gemm_tn_kernel<<<grd, blk>>>(text, gate_w, 0, 0);
    }
    // gs = struct @ ws^T (woff=H)
    {
        dim3 blk(16, 16);
        dim3 grd(H_DIM / BN, S_DIM / BM);
        gemm_tn_kernel<<<grd, blk>>>(sstruct, gate_w, H_DIM, 1);
    }
    // fused gates + enrichment + layernorm
    {
        fuse_kernel<<<T_DIM / TB, H_DIM>>>(text, sstruct, mask,
                                           gate_b, gamma, beta,
                                           enriched, gates);
    }
}

// round 3
// speedup vs baseline: 1.3082x; 1.3082x over previous
#include <cuda_runtime.h>
#include <cuda_bf16.h>
#include <math.h>

#define T_DIM 1024
#define S_DIM 128
#define H_DIM 512
#define LN_EPS 1e-5f

// Scratch (allocation-free rule: __device__ globals)
__device__ float d_gt[T_DIM * H_DIM];   // text   @ wt^T  (1024 x 512)
__device__ float d_gs[S_DIM * H_DIM];   // struct @ ws^T  (128  x 512)

// ---------------------------------------------------------------------------
// Combined GEMM for gt and gs in ONE launch.
// Combined row space: rows [0,1024) -> gt from text (woff=0)
//                     rows [1024,1152) -> gs from struct (woff=512)
// C[r,i] = sum_k A[r,k] * W[i*1024 + woff + k]
// Tiles: 64(M) x 32(N) x 32(K), 128 threads, each thread 4x4.
// ---------------------------------------------------------------------------
#define GM 64
#define GN 32
#define GK 32

__global__ __launch_bounds__(128) void gemm_all_kernel(
    const float* __restrict__ text, const float* __restrict__ sstruct,
    const float* __restrict__ W)
{
    __shared__ float As[GM][GK + 1];
    __shared__ float Bs[GN][GK + 1];

    const int tid = threadIdx.x;
    const int tx  = tid & 7;     // 0..7   (N dir, 4 cols each)
    const int ty  = tid >> 3;    // 0..15  (M dir, 4 rows each)
    const int bcol  = blockIdx.x * GN;
    const int browg = blockIdx.y * GM;

    const float* __restrict__ A;
    float* __restrict__ C;
    int arow, woff;
    if (browg < T_DIM) { A = text;    arow = browg;          woff = 0;     C = d_gt; }
    else               { A = sstruct; arow = browg - T_DIM;  woff = H_DIM; C = d_gs; }

    float acc[4][4];
    #pragma unroll
    for (int i = 0; i < 4; i++)
        #pragma unroll
        for (int j = 0; j < 4; j++) acc[i][j] = 0.f;

    for (int k0 = 0; k0 < H_DIM; k0 += GK) {
        // A tile: 64x32 floats = 512 float4; 4 per thread
        #pragma unroll
        for (int i = 0; i < 4; i++) {
            int lin = tid + i * 128;
            int r   = lin >> 3;
            int c4  = (lin & 7) * 4;
            float4 v = *(const float4*)(A + (size_t)(arow + r) * H_DIM + k0 + c4);
            As[r][c4]     = v.x; As[r][c4 + 1] = v.y;
            As[r][c4 + 2] = v.z; As[r][c4 + 3] = v.w;
        }
        // B tile: 32x32 floats = 256 float4; 2 per thread
        #pragma unroll
        for (int i = 0; i < 2; i++) {
            int lin = tid + i * 128;
            int r   = lin >> 3;
            int c4  = (lin & 7) * 4;
            float4 v = *(const float4*)(W + (size_t)(bcol + r) * 1024 + woff + k0 + c4);
            Bs[r][c4]     = v.x; Bs[r][c4 + 1] = v.y;
            Bs[r][c4 + 2] = v.z; Bs[r][c4 + 3] = v.w;
        }
        __syncthreads();

        #pragma unroll
        for (int k = 0; k < GK; k++) {
            float a[4], b[4];
            #pragma unroll
            for (int i = 0; i < 4; i++) a[i] = As[ty * 4 + i][k];
            #pragma unroll
            for (int j = 0; j < 4; j++) b[j] = Bs[tx * 4 + j][k];
            #pragma unroll
            for (int i = 0; i < 4; i++)
                #pragma unroll
                for (int j = 0; j < 4; j++)
                    acc[i][j] = fmaf(a[i], b[j], acc[i][j]);
        }
        __syncthreads();
    }

    #pragma unroll
    for (int i = 0; i < 4; i++) {
        float4 v = make_float4(acc[i][0], acc[i][1], acc[i][2], acc[i][3]);
        *(float4*)(C + (size_t)(arow + ty * 4 + i) * H_DIM + bcol + tx * 4) = v;
    }
}

// ---------------------------------------------------------------------------
// Fused: gates = relu(gt + gs + b) * mask; enrichment = sum_s gates*struct;
//        enriched = LN(text + enrichment).
// Block: 256 threads. tg = tid/128 picks a pair of t-rows; h4 = tid%128
// picks a float4 of H. Block covers TB=4 t-rows. All stores are STG.128.
// ---------------------------------------------------------------------------
#define TB 4

__global__ __launch_bounds__(256) void fuse_kernel(
    const float* __restrict__ text,
    const float* __restrict__ sstruct,
    const int*   __restrict__ mask,
    const float* __restrict__ gate_b,
    const float* __restrict__ gamma,
    const float* __restrict__ beta,
    float* __restrict__ enriched,   // (T, H)
    float* __restrict__ gates)      // (T, S, H)
{
    const int tid = threadIdx.x;
    const int h4  = tid & 127;      // float4 index over H/4 = 128
    const int tg  = tid >> 7;       // 0 or 1 -> rows {0,1} or {2,3}
    const int h   = h4 * 4;
    const int t0  = blockIdx.x * TB;

    __shared__ float msk[TB][S_DIM];
    __shared__ float red[2][TB][4];

    // Mask tile as float (512 ints, 2 per thread)
    #pragma unroll
    for (int i = tid; i < TB * S_DIM; i += 256) {
        int tt = i >> 7, s = i & (S_DIM - 1);
        msk[tt][s] = (float)mask[(size_t)(t0 + tt) * S_DIM + s];
    }
    __syncthreads();

    const float4 bias = *(const float4*)(gate_b + h);
    const int r0 = t0 + tg * 2;

    float4 gtb[2], acc[2];
    #pragma unroll
    for (int j = 0; j < 2; j++) {
        float4 g = *(const float4*)(d_gt + (size_t)(r0 + j) * H_DIM + h);
        gtb[j] = make_float4(g.x + bias.x, g.y + bias.y, g.z + bias.z, g.w + bias.w);
        acc[j] = make_float4(0.f, 0.f, 0.f, 0.f);
    }

    #pragma unroll 4
    for (int s = 0; s < S_DIM; s++) {
        const float4 gsv = *(const float4*)(d_gs    + (size_t)s * H_DIM + h);
        const float4 sv  = *(const float4*)(sstruct + (size_t)s * H_DIM + h);
        #pragma unroll
        for (int j = 0; j < 2; j++) {
            const float m = msk[tg * 2 + j][s];
            float4 g;
            g.x = fmaxf(gtb[j].x + gsv.x, 0.f) * m;
            g.y = fmaxf(gtb[j].y + gsv.y, 0.f) * m;
            g.z = fmaxf(gtb[j].z + gsv.z, 0.f) * m;
            g.w = fmaxf(gtb[j].w + gsv.w, 0.f) * m;
            *(float4*)(gates + ((size_t)(r0 + j) * S_DIM + s) * H_DIM + h) = g;
            acc[j].x = fmaf(g.x, sv.x, acc[j].x);
            acc[j].y = fmaf(g.y, sv.y, acc[j].y);
            acc[j].z = fmaf(g.z, sv.z, acc[j].z);
            acc[j].w = fmaf(g.w, sv.w, acc[j].w);
        }
    }

    // LayerNorm: each row is owned by 128 threads = 4 warps of its tg group.
    const int lane = tid & 31;
    const int wg   = (tid >> 5) & 3;     // warp index within tg group

    float4 xv[2];
    #pragma unroll
    for (int j = 0; j < 2; j++) {
        const int r = r0 + j;
        float4 tx4 = *(const float4*)(text + (size_t)r * H_DIM + h);
        float4 x;
        x.x = tx4.x + acc[j].x;
        x.y = tx4.y + acc[j].y;
        x.z = tx4.z + acc[j].z;
        x.w = tx4.w + acc[j].w;
        xv[j] = x;
        float s1 = x.x + x.y + x.z + x.w;
        float s2 = x.x * x.x + x.y * x.y + x.z * x.z + x.w * x.w;
        #pragma unroll
        for (int o = 16; o > 0; o >>= 1) {
            s1 += __shfl_xor_sync(0xFFFFFFFFu, s1, o);
            s2 += __shfl_xor_sync(0xFFFFFFFFu, s2, o);
        }
        if (lane == 0) {
            red[0][tg * 2 + j][wg] = s1;
            red[1][tg * 2 + j][wg] = s2;
        }
    }
    __syncthreads();

    const float4 gm = *(const float4*)(gamma + h);
    const float4 bt = *(const float4*)(beta  + h);
    #pragma unroll
    for (int j = 0; j < 2; j++) {
        const int rr = tg * 2 + j;
        float s1 = red[0][rr][0] + red[0][rr][1] + red[0][rr][2] + red[0][rr][3];
        float s2 = red[1][rr][0] + red[1][rr][1] + red[1][rr][2] + red[1][rr][3];
        float mu  = s1 * (1.f / H_DIM);
        float var = s2 * (1.f / H_DIM) - mu * mu;
        float inv = rsqrtf(var + LN_EPS);
        float4 o;
        o.x = (xv[j].x - mu) * inv * gm.x + bt.x;
        o.y = (xv[j].y - mu) * inv * gm.y + bt.y;
        o.z = (xv[j].z - mu) * inv * gm.z + bt.z;
        o.w = (xv[j].w - mu) * inv * gm.w + bt.w;
        *(float4*)(enriched + (size_t)(r0 + j) * H_DIM + h) = o;
    }
}

// ---------------------------------------------------------------------------
extern "C" void kernel_launch(void* const* d_in, const int* in_sizes, int n_in,
                              void* d_out, int out_size)
{
    const float* text    = (const float*)d_in[0];
    const float* sstruct = (const float*)d_in[1];
    const int*   mask    = (const int*)  d_in[2];
    const float* gate_w  = (const float*)d_in[3];
    const float* gate_b  = (const float*)d_in[4];
    const float* gamma   = (const float*)d_in[5];
    const float* beta    = (const float*)d_in[6];

    float* enriched = (float*)d_out;
    float* gates    = (float*)d_out + (size_t)T_DIM * H_DIM;

    {
        dim3 grd(H_DIM / GN, (T_DIM + S_DIM) / GM);   // 16 x 18 = 288 blocks
        gemm_all_kernel<<<grd, 128>>>(text, sstruct, gate_w);
    }
    {
        fuse_kernel<<<T_DIM / TB, 256>>>(text, sstruct, mask,
                                         gate_b, gamma, beta,
                                         enriched, gates);
    }
}

// round 4
// speedup vs baseline: 1.9565x; 1.4956x over previous
#include <cuda_runtime.h>
#include <cuda_bf16.h>
#include <math.h>

#define T_DIM 1024
#define S_DIM 128
#define H_DIM 512
#define LN_EPS 1e-5f

// Scratch (allocation-free rule: __device__ globals)
__device__ float d_gt[T_DIM * H_DIM];   // text   @ wt^T  (1024 x 512)
__device__ float d_gs[S_DIM * H_DIM];   // struct @ ws^T  (128  x 512)

// ---------------------------------------------------------------------------
// Combined GEMM for gt and gs in ONE launch (unchanged from round 3 — it
// hit ~27us; fuse dominates).
// ---------------------------------------------------------------------------
#define GM 64
#define GN 32
#define GK 32

__global__ __launch_bounds__(128) void gemm_all_kernel(
    const float* __restrict__ text, const float* __restrict__ sstruct,
    const float* __restrict__ W)
{
    __shared__ float As[GM][GK + 1];
    __shared__ float Bs[GN][GK + 1];

    const int tid = threadIdx.x;
    const int tx  = tid & 7;
    const int ty  = tid >> 3;
    const int bcol  = blockIdx.x * GN;
    const int browg = blockIdx.y * GM;

    const float* __restrict__ A;
    float* __restrict__ C;
    int arow, woff;
    if (browg < T_DIM) { A = text;    arow = browg;          woff = 0;     C = d_gt; }
    else               { A = sstruct; arow = browg - T_DIM;  woff = H_DIM; C = d_gs; }

    float acc[4][4];
    #pragma unroll
    for (int i = 0; i < 4; i++)
        #pragma unroll
        for (int j = 0; j < 4; j++) acc[i][j] = 0.f;

    for (int k0 = 0; k0 < H_DIM; k0 += GK) {
        #pragma unroll
        for (int i = 0; i < 4; i++) {
            int lin = tid + i * 128;
            int r   = lin >> 3;
            int c4  = (lin & 7) * 4;
            float4 v = *(const float4*)(A + (size_t)(arow + r) * H_DIM + k0 + c4);
            As[r][c4]     = v.x; As[r][c4 + 1] = v.y;
            As[r][c4 + 2] = v.z; As[r][c4 + 3] = v.w;
        }
        #pragma unroll
        for (int i = 0; i < 2; i++) {
            int lin = tid + i * 128;
            int r   = lin >> 3;
            int c4  = (lin & 7) * 4;
            float4 v = *(const float4*)(W + (size_t)(bcol + r) * 1024 + woff + k0 + c4);
            Bs[r][c4]     = v.x; Bs[r][c4 + 1] = v.y;
            Bs[r][c4 + 2] = v.z; Bs[r][c4 + 3] = v.w;
        }
        __syncthreads();

        #pragma unroll
        for (int k = 0; k < GK; k++) {
            float a[4], b[4];
            #pragma unroll
            for (int i = 0; i < 4; i++) a[i] = As[ty * 4 + i][k];
            #pragma unroll
            for (int j = 0; j < 4; j++) b[j] = Bs[tx * 4 + j][k];
            #pragma unroll
            for (int i = 0; i < 4; i++)
                #pragma unroll
                for (int j = 0; j < 4; j++)
                    acc[i][j] = fmaf(a[i], b[j], acc[i][j]);
        }
        __syncthreads();
    }

    #pragma unroll
    for (int i = 0; i < 4; i++) {
        float4 v = make_float4(acc[i][0], acc[i][1], acc[i][2], acc[i][3]);
        *(float4*)(C + (size_t)(arow + ty * 4 + i) * H_DIM + bcol + tx * 4) = v;
    }
}

// ---------------------------------------------------------------------------
// Fused gates + enrichment + LN.
// TB=2 t-rows per block, 256 threads: tg = tid>>7 picks the row, h4 = tid&127
// picks the float4 of H. One STG.128 (streaming) per thread per s.
// grid = 512 -> ~3.5 CTAs/SM, ~28 warps/SM.
// ---------------------------------------------------------------------------
#define TB 2

__global__ __launch_bounds__(256) void fuse_kernel(
    const float* __restrict__ text,
    const float* __restrict__ sstruct,
    const int*   __restrict__ mask,
    const float* __restrict__ gate_b,
    const float* __restrict__ gamma,
    const float* __restrict__ beta,
    float* __restrict__ enriched,   // (T, H)
    float* __restrict__ gates)      // (T, S, H)
{
    const int tid = threadIdx.x;
    const int h4  = tid & 127;      // 0..127 -> float4 over H
    const int tg  = tid >> 7;       // 0..1   -> t-row within block
    const int h   = h4 * 4;
    const int t0  = blockIdx.x * TB;
    const int r   = t0 + tg;

    __shared__ float msk[TB][S_DIM];
    __shared__ float red[2][TB][4];

    // Mask tile as float (256 ints, 1 per thread)
    {
        int tt = tid >> 7, s = tid & (S_DIM - 1);
        msk[tt][s] = (float)mask[(size_t)(t0 + tt) * S_DIM + s];
    }
    __syncthreads();

    const float4 bias = *(const float4*)(gate_b + h);
    float4 gtb, acc;
    {
        float4 g = *(const float4*)(d_gt + (size_t)r * H_DIM + h);
        gtb = make_float4(g.x + bias.x, g.y + bias.y, g.z + bias.z, g.w + bias.w);
        acc = make_float4(0.f, 0.f, 0.f, 0.f);
    }

    float* __restrict__ grow = gates + (size_t)r * S_DIM * H_DIM + h;

    #pragma unroll 4
    for (int s = 0; s < S_DIM; s++) {
        const float4 gsv = *(const float4*)(d_gs    + (size_t)s * H_DIM + h);
        const float4 sv  = *(const float4*)(sstruct + (size_t)s * H_DIM + h);
        const float  m   = msk[tg][s];
        float4 g;
        g.x = fmaxf(gtb.x + gsv.x, 0.f) * m;
        g.y = fmaxf(gtb.y + gsv.y, 0.f) * m;
        g.z = fmaxf(gtb.z + gsv.z, 0.f) * m;
        g.w = fmaxf(gtb.w + gsv.w, 0.f) * m;
        __stcs((float4*)(grow + (size_t)s * H_DIM), g);   // streaming store
        acc.x = fmaf(g.x, sv.x, acc.x);
        acc.y = fmaf(g.y, sv.y, acc.y);
        acc.z = fmaf(g.z, sv.z, acc.z);
        acc.w = fmaf(g.w, sv.w, acc.w);
    }

    // LayerNorm: row owned by its 128-thread tg group (4 warps).
    const int lane = tid & 31;
    const int wg   = (tid >> 5) & 3;

    float4 x;
    {
        float4 tx4 = *(const float4*)(text + (size_t)r * H_DIM + h);
        x.x = tx4.x + acc.x;
        x.y = tx4.y + acc.y;
        x.z = tx4.z + acc.z;
        x.w = tx4.w + acc.w;
        float s1 = x.x + x.y + x.z + x.w;
        float s2 = x.x * x.x + x.y * x.y + x.z * x.z + x.w * x.w;
        #pragma unroll
        for (int o = 16; o > 0; o >>= 1) {
            s1 += __shfl_xor_sync(0xFFFFFFFFu, s1, o);
            s2 += __shfl_xor_sync(0xFFFFFFFFu, s2, o);
        }
        if (lane == 0) { red[0][tg][wg] = s1; red[1][tg][wg] = s2; }
    }
    __syncthreads();

    const float4 gm = *(const float4*)(gamma + h);
    const float4 bt = *(const float4*)(beta  + h);
    {
        float s1 = red[0][tg][0] + red[0][tg][1] + red[0][tg][2] + red[0][tg][3];
        float s2 = red[1][tg][0] + red[1][tg][1] + red[1][tg][2] + red[1][tg][3];
        float mu  = s1 * (1.f / H_DIM);
        float var = s2 * (1.f / H_DIM) - mu * mu;
        float inv = rsqrtf(var + LN_EPS);
        float4 o;
        o.x = (x.x - mu) * inv * gm.x + bt.x;
        o.y = (x.y - mu) * inv * gm.y + bt.y;
        o.z = (x.z - mu) * inv * gm.z + bt.z;
        o.w = (x.w - mu) * inv * gm.w + bt.w;
        *(float4*)(enriched + (size_t)r * H_DIM + h) = o;
    }
}

// ---------------------------------------------------------------------------
extern "C" void kernel_launch(void* const* d_in, const int* in_sizes, int n_in,
                              void* d_out, int out_size)
{
    const float* text    = (const float*)d_in[0];
    const float* sstruct = (const float*)d_in[1];
    const int*   mask    = (const int*)  d_in[2];
    const float* gate_w  = (const float*)d_in[3];
    const float* gate_b  = (const float*)d_in[4];
    const float* gamma   = (const float*)d_in[5];
    const float* beta    = (const float*)d_in[6];

    float* enriched = (float*)d_out;
    float* gates    = (float*)d_out + (size_t)T_DIM * H_DIM;

    {
        dim3 grd(H_DIM / GN, (T_DIM + S_DIM) / GM);   // 16 x 18 = 288 blocks
        gemm_all_kernel<<<grd, 128>>>(text, sstruct, gate_w);
    }
    {
        fuse_kernel<<<T_DIM / TB, 256>>>(text, sstruct, mask,
                                         gate_b, gamma, beta,
                                         enriched, gates);
    }
}